// round 8
// baseline (speedup 1.0000x reference)
#include <cuda_runtime.h>
#include <cuda_bf16.h>
#include <math.h>

// Problem constants (fixed by the dataset)
#define MAXN 50048
#define MAXE 800000
#define INDIM 256
#define ODIM 128
#define SCAN_B 256
#define MAXB ((MAXN + SCAN_B - 1) / SCAN_B)

// Scratch (device globals; no allocation allowed)
__device__ float g_h[(size_t)MAXN * ODIM];        // h_prime [N,128]
__device__ float g_edst[MAXN];                    // e_dst per node (incl bias)
__device__ float g_esrc[MAXN];                    // e_src per node (incl bias)
__device__ int   g_deg[MAXN];                     // in-degree (zero at load; scan re-zeroes)
__device__ int   g_row[MAXN + 1];                 // CSR row offsets
__device__ int   g_rank[MAXE];                    // rank of edge within its dst bucket
__device__ unsigned long long g_pack[MAXE];       // packed (score<<32 | src) per bucketed edge
__device__ int   g_scanflag[MAXB];                // decoupled-lookback flags (reset by scatter)
__device__ int   g_scanagg[MAXB];                 // block aggregates
__device__ int   g_scaninc[MAXB];                 // block inclusive prefixes

// ---------------------------------------------------------------------------
// helpers
// ---------------------------------------------------------------------------
__device__ __forceinline__ void tf32_split(float f, float& h, float& l) {
    unsigned hb;
    asm("cvt.rna.tf32.f32 %0, %1;" : "=r"(hb) : "f"(f));
    h = __uint_as_float(hb);
    float r = f - h;
    unsigned lb;
    asm("cvt.rna.tf32.f32 %0, %1;" : "=r"(lb) : "f"(r));
    l = __uint_as_float(lb);
}

__device__ __forceinline__ void mma_tf32(float* d, const float* a, const float* b) {
    asm volatile(
        "mma.sync.aligned.m16n8k8.row.col.f32.tf32.tf32.f32 "
        "{%0,%1,%2,%3}, {%4,%5,%6,%7}, {%8,%9}, {%0,%1,%2,%3};"
        : "+f"(d[0]), "+f"(d[1]), "+f"(d[2]), "+f"(d[3])
        : "r"(__float_as_uint(a[0])), "r"(__float_as_uint(a[1])),
          "r"(__float_as_uint(a[2])), "r"(__float_as_uint(a[3])),
          "r"(__float_as_uint(b[0])), "r"(__float_as_uint(b[1])));
}

__device__ __forceinline__ void cp16(unsigned saddr, const void* gaddr, int pred) {
    asm volatile("cp.async.cg.shared.global [%0], [%1], 16, %2;"
                 :: "r"(saddr), "l"(gaddr), "r"(pred ? 16 : 0));
}
__device__ __forceinline__ void cp_commit() { asm volatile("cp.async.commit_group;"); }
template <int N>
__device__ __forceinline__ void cp_wait() { asm volatile("cp.async.wait_group %0;" :: "n"(N)); }

// ---------------------------------------------------------------------------
// 1: fused mega-kernel: TC GEMM + logits epilogue + (count+rank) blocks
// ---------------------------------------------------------------------------
#define AST 20     // A smem row stride (floats): conflict-free fragment loads
#define WST 136    // W smem row stride (floats): conflict-free fragment loads

__global__ __launch_bounds__(256)
void gemm_fused_kernel(const float* __restrict__ A, const float* __restrict__ W,
                       const float* __restrict__ a_dst, const float* __restrict__ b_dst,
                       const float* __restrict__ a_src, const float* __restrict__ b_src,
                       const int* __restrict__ edge_dst,
                       int n, int E, int gemm_blocks) {
    __shared__ float Ab[2][128 * AST];
    __shared__ float Wb[2][16 * WST];
    __shared__ float s_ed[128], s_es[128];

    const int tid = threadIdx.x;

    // ---------------- count + rank path ----------------
    if ((int)blockIdx.x >= gemm_blocks) {
        const int stride = (gridDim.x - gemm_blocks) * 256;
        for (int e = (blockIdx.x - gemm_blocks) * 256 + tid; e < E; e += stride) {
            int r = atomicAdd(&g_deg[edge_dst[e]], 1);
            g_rank[e] = r;
        }
        return;
    }

    // ---------------- GEMM path ----------------
    const int lane = tid & 31;
    const int wid  = tid >> 5;
    const int wm   = wid >> 2;         // 0..1
    const int wn   = wid & 3;          // 0..3
    const int block_row = blockIdx.x * 128;
    const int q  = lane >> 2;          // 0..7
    const int cc = lane & 3;           // 0..3

    const int ac0 = tid * 2;
    const int wc0 = tid * 2;

    const int   gr0  = block_row + (ac0 >> 2);
    const int   gr1  = block_row + ((ac0 + 1) >> 2);
    const float* gA0 = A + (size_t)gr0 * INDIM + ((ac0 & 3) * 4);
    const float* gA1 = A + (size_t)gr1 * INDIM + (((ac0 + 1) & 3) * 4);
    const int   p0   = gr0 < n;
    const int   p1   = gr1 < n;
    const float* gW0 = W + (size_t)(wc0 >> 5) * ODIM + ((wc0 & 31) * 4);
    const float* gW1 = W + (size_t)((wc0 + 1) >> 5) * ODIM + (((wc0 + 1) & 31) * 4);

    const unsigned sA0 = (unsigned)__cvta_generic_to_shared(&Ab[0][0])
                       + (unsigned)(((ac0 >> 2) * AST + (ac0 & 3) * 4) * 4);
    const unsigned sA1 = (unsigned)__cvta_generic_to_shared(&Ab[0][0])
                       + (unsigned)((((ac0 + 1) >> 2) * AST + ((ac0 + 1) & 3) * 4) * 4);
    const unsigned sW0 = (unsigned)__cvta_generic_to_shared(&Wb[0][0])
                       + (unsigned)(((wc0 >> 5) * WST + (wc0 & 31) * 4) * 4);
    const unsigned sW1 = (unsigned)__cvta_generic_to_shared(&Wb[0][0])
                       + (unsigned)((((wc0 + 1) >> 5) * WST + ((wc0 + 1) & 31) * 4) * 4);
    const unsigned abuf = 128 * AST * 4;
    const unsigned wbuf = 16 * WST * 4;

    auto issue = [&](int s, int buf) {
        cp16(sA0 + buf * abuf, gA0 + s * 16, p0);
        cp16(sA1 + buf * abuf, gA1 + s * 16, p1);
        cp16(sW0 + buf * wbuf, gW0 + (size_t)s * 16 * ODIM, 1);
        cp16(sW1 + buf * wbuf, gW1 + (size_t)s * 16 * ODIM, 1);
        cp_commit();
    };

    float acc[4][4][4];
#pragma unroll
    for (int mt = 0; mt < 4; mt++)
#pragma unroll
        for (int nt = 0; nt < 4; nt++)
#pragma unroll
            for (int j = 0; j < 4; j++) acc[mt][nt][j] = 0.f;

    issue(0, 0);

    const int NS = INDIM / 16;   // 16 slabs
    for (int s = 0; s < NS; s++) {
        const int buf = s & 1;
        if (s + 1 < NS) { issue(s + 1, buf ^ 1); cp_wait<1>(); }
        else            { cp_wait<0>(); }
        __syncthreads();

        const float* Ac = &Ab[buf][0];
        const float* Wc = &Wb[buf][0];

#pragma unroll
        for (int ks = 0; ks < 16; ks += 8) {
            float bh[4][2], bl[4][2];
#pragma unroll
            for (int nt = 0; nt < 4; nt++) {
                int col = wn * 32 + nt * 8 + q;
                float r0 = Wc[(ks + cc) * WST + col];
                float r1 = Wc[(ks + cc + 4) * WST + col];
                tf32_split(r0, bh[nt][0], bl[nt][0]);
                tf32_split(r1, bh[nt][1], bl[nt][1]);
            }
#pragma unroll
            for (int mt = 0; mt < 4; mt++) {
                int r = wm * 64 + mt * 16 + q;
                int c = ks + cc;
                float a0 = Ac[r * AST + c];
                float a1 = Ac[(r + 8) * AST + c];
                float a2 = Ac[r * AST + c + 4];
                float a3 = Ac[(r + 8) * AST + c + 4];
                float ah[4], al[4];
                tf32_split(a0, ah[0], al[0]);
                tf32_split(a1, ah[1], al[1]);
                tf32_split(a2, ah[2], al[2]);
                tf32_split(a3, ah[3], al[3]);
#pragma unroll
                for (int nt = 0; nt < 4; nt++) {
                    mma_tf32(acc[mt][nt], ah, bh[nt]);   // hi*hi
                    mma_tf32(acc[mt][nt], al, bh[nt]);   // lo*hi
                    mma_tf32(acc[mt][nt], ah, bl[nt]);   // hi*lo
                }
            }
        }
        __syncthreads();
    }

    // --- epilogue 1: store h' ---
#pragma unroll
    for (int mt = 0; mt < 4; mt++) {
#pragma unroll
        for (int nt = 0; nt < 4; nt++) {
            int row = block_row + wm * 64 + mt * 16 + q;
            int col = wn * 32 + nt * 8 + cc * 2;
            if (row < n)
                *(float2*)(g_h + (size_t)row * ODIM + col) =
                    make_float2(acc[mt][nt][0], acc[mt][nt][1]);
            if (row + 8 < n)
                *(float2*)(g_h + (size_t)(row + 8) * ODIM + col) =
                    make_float2(acc[mt][nt][2], acc[mt][nt][3]);
        }
    }

    // --- epilogue 2: fused logits e_dst/e_src ---
    if (tid < 128) { s_ed[tid] = 0.f; s_es[tid] = 0.f; }
    __syncthreads();
#pragma unroll
    for (int mt = 0; mt < 4; mt++) {
        float pd0 = 0.f, ps0 = 0.f, pd1 = 0.f, ps1 = 0.f;
#pragma unroll
        for (int nt = 0; nt < 4; nt++) {
            int col = wn * 32 + nt * 8 + cc * 2;
            float2 ad = *(const float2*)(a_dst + col);
            float2 as = *(const float2*)(a_src + col);
            pd0 += acc[mt][nt][0] * ad.x + acc[mt][nt][1] * ad.y;
            ps0 += acc[mt][nt][0] * as.x + acc[mt][nt][1] * as.y;
            pd1 += acc[mt][nt][2] * ad.x + acc[mt][nt][3] * ad.y;
            ps1 += acc[mt][nt][2] * as.x + acc[mt][nt][3] * as.y;
        }
#pragma unroll
        for (int o = 1; o < 4; o <<= 1) {
            pd0 += __shfl_xor_sync(0xffffffffu, pd0, o);
            ps0 += __shfl_xor_sync(0xffffffffu, ps0, o);
            pd1 += __shfl_xor_sync(0xffffffffu, pd1, o);
            ps1 += __shfl_xor_sync(0xffffffffu, ps1, o);
        }
        if (cc == 0) {
            int r0 = wm * 64 + mt * 16 + q;
            atomicAdd(&s_ed[r0], pd0);     atomicAdd(&s_es[r0], ps0);
            atomicAdd(&s_ed[r0 + 8], pd1); atomicAdd(&s_es[r0 + 8], ps1);
        }
    }
    __syncthreads();
    if (tid < 128) {
        int gr = block_row + tid;
        if (gr < n) {
            g_edst[gr] = s_ed[tid] + *b_dst;
            g_esrc[gr] = s_es[tid] + *b_src;
        }
    }
}

// ---------------------------------------------------------------------------
// 2: single-pass decoupled-lookback scan: g_deg -> g_row (+re-zero g_deg)
//    flags are zero on entry (zero-init at load; reset by scatter each call)
// ---------------------------------------------------------------------------
__global__ __launch_bounds__(SCAN_B)
void scan_kernel(int nb, int n) {
    __shared__ int wsum[8];
    __shared__ int s_off;
    const int tid  = threadIdx.x;
    const int lane = tid & 31;
    const int w    = tid >> 5;
    const int b    = blockIdx.x;
    const int i    = b * SCAN_B + tid;

    int v = 0;
    if (i < n) { v = g_deg[i]; g_deg[i] = 0; }   // restore zero invariant
    int incl = v;
#pragma unroll
    for (int o = 1; o < 32; o <<= 1) {
        int u = __shfl_up_sync(0xffffffffu, incl, o);
        if (lane >= o) incl += u;
    }
    if (lane == 31) wsum[w] = incl;
    __syncthreads();
    if (w == 0 && lane < 8) {
        int s = wsum[lane];
#pragma unroll
        for (int o = 1; o < 8; o <<= 1) {
            int u = __shfl_up_sync(0x000000ffu, s, o);
            if (lane >= o) s += u;
        }
        wsum[lane] = s;
    }
    __syncthreads();
    const int tot = wsum[7];

    if (tid == 0) {
        if (b == 0) {
            g_scaninc[0] = tot;
            __threadfence();
            atomicExch(&g_scanflag[0], 2);
            s_off = 0;
        } else {
            g_scanagg[b] = tot;
            __threadfence();
            atomicExch(&g_scanflag[b], 1);
            // lookback
            int prefix = 0;
            int j = b - 1;
            while (true) {
                int f;
                do { f = atomicAdd(&g_scanflag[j], 0); } while (f == 0);
                if (f == 2) { prefix += atomicAdd(&g_scaninc[j], 0); break; }
                prefix += atomicAdd(&g_scanagg[j], 0);
                j--;
            }
            g_scaninc[b] = prefix + tot;
            __threadfence();
            atomicExch(&g_scanflag[b], 2);
            s_off = prefix;
        }
    }
    __syncthreads();

    int excl = incl - v + (w > 0 ? wsum[w - 1] : 0) + s_off;
    if (i < n) g_row[i] = excl;
    if (b == nb - 1 && tid == 0) g_row[n] = s_off + tot;
}

// ---------------------------------------------------------------------------
// 3: bucket edges (atomic-free: position = row[dst] + rank); reset scan flags
// ---------------------------------------------------------------------------
__global__ void scatter_kernel(const int* __restrict__ edge_src,
                               const int* __restrict__ edge_dst, int E) {
    int e = blockIdx.x * blockDim.x + threadIdx.x;
    if (e < MAXB) g_scanflag[e] = 0;          // reset for next replay
    if (e < E) {
        int d = edge_dst[e];
        int s = edge_src[e];
        float sc = g_edst[d] + g_esrc[s];
        sc = sc >= 0.f ? sc : 0.2f * sc;
        int p = g_row[d] + g_rank[e];
        g_pack[p] = ((unsigned long long)__float_as_uint(sc) << 32) | (unsigned)s;
    }
}

// ---------------------------------------------------------------------------
// 4: per-dst online softmax + weighted aggregation, one warp per dst node
// ---------------------------------------------------------------------------
__global__ __launch_bounds__(256)
void agg_kernel(const float* __restrict__ out_bias,
                float* __restrict__ out, int n) {
    const int gw   = (blockIdx.x * blockDim.x + threadIdx.x) >> 5;
    const int lane = threadIdx.x & 31;
    if (gw >= n) return;

    const int beg = g_row[gw];
    const int end = g_row[gw + 1];

    float m = -INFINITY, ssum = 0.f;
    for (int i = beg + lane; i < end; i += 32) {
        float sc = __uint_as_float((unsigned)(g_pack[i] >> 32));
        if (sc > m) {
            ssum = ssum * __expf(m - sc) + 1.f;
            m = sc;
        } else {
            ssum += __expf(sc - m);
        }
    }
    float M = m;
#pragma unroll
    for (int o = 16; o; o >>= 1) M = fmaxf(M, __shfl_xor_sync(0xffffffffu, M, o));
    float part = (m == -INFINITY) ? 0.f : ssum * __expf(m - M);
#pragma unroll
    for (int o = 16; o; o >>= 1) part += __shfl_xor_sync(0xffffffffu, part, o);
    const float inv = 1.f / fmaxf(part, 1e-12f);

    const int c = lane * 4;
    float a0 = 0.f, a1 = 0.f, a2 = 0.f, a3 = 0.f;
#pragma unroll 2
    for (int i = beg; i < end; i++) {
        unsigned long long pk = g_pack[i];
        int s = (int)(unsigned)pk;
        float al = __expf(__uint_as_float((unsigned)(pk >> 32)) - M) * inv;
        float4 v = *(const float4*)(g_h + (size_t)s * ODIM + c);
        a0 += al * v.x; a1 += al * v.y; a2 += al * v.z; a3 += al * v.w;
    }

    float4 b4 = *(const float4*)(out_bias + c);
    a0 += b4.x; a1 += b4.y; a2 += b4.z; a3 += b4.w;
    float4 o4;
    o4.x = a0 > 0.f ? a0 : expm1f(a0);
    o4.y = a1 > 0.f ? a1 : expm1f(a1);
    o4.z = a2 > 0.f ? a2 : expm1f(a2);
    o4.w = a3 > 0.f ? a3 : expm1f(a3);
    *(float4*)(out + (size_t)gw * ODIM + c) = o4;
}

// ---------------------------------------------------------------------------
extern "C" void kernel_launch(void* const* d_in, const int* in_sizes, int n_in,
                              void* d_out, int out_size) {
    const float* inputs   = (const float*)d_in[0];
    const int*   edge_src = (const int*)d_in[1];
    const int*   edge_dst = (const int*)d_in[2];
    const float* W_seq    = (const float*)d_in[3];
    const float* a_dst    = (const float*)d_in[4];
    const float* b_dst    = (const float*)d_in[5];
    const float* a_src    = (const float*)d_in[6];
    const float* b_src    = (const float*)d_in[7];
    const float* out_bias = (const float*)d_in[8];
    float* out = (float*)d_out;

    const int n = in_sizes[0] / INDIM;
    const int E = in_sizes[1];
    const int nb = (n + SCAN_B - 1) / SCAN_B;
    const int gemm_blocks = (n + 127) / 128;
    const int cnt_blocks  = 1024;

    gemm_fused_kernel<<<gemm_blocks + cnt_blocks, 256>>>(
        inputs, W_seq, a_dst, b_dst, a_src, b_src, edge_dst, n, E, gemm_blocks);
    scan_kernel<<<nb, SCAN_B>>>(nb, n);
    scatter_kernel<<<(E + 255) / 256, 256>>>(edge_src, edge_dst, E);
    agg_kernel<<<(n * 32 + 255) / 256, 256>>>(out_bias, out, n);
}

// round 9
// speedup vs baseline: 1.1281x; 1.1281x over previous
#include <cuda_runtime.h>
#include <cuda_bf16.h>
#include <math.h>

// Problem constants (fixed by the dataset)
#define MAXN 50048
#define MAXE 800000
#define INDIM 256
#define ODIM 128
#define SCAN_B 256
#define MAXB ((MAXN + SCAN_B - 1) / SCAN_B)

// Scratch (device globals; no allocation allowed)
__device__ float g_h[(size_t)MAXN * ODIM];        // h_prime [N,128]
__device__ float g_edst[MAXN];                    // e_dst per node (incl bias)
__device__ float g_esrc[MAXN];                    // e_src per node (incl bias)
__device__ int   g_deg[MAXN];                     // in-degree (zero at load; scanA re-zeroes)
__device__ int   g_row[MAXN + 1];                 // CSR row offsets
__device__ int   g_cur[MAXN];                     // scatter cursors
__device__ unsigned long long g_pack[MAXE];       // packed (score<<32 | src) per bucketed edge
__device__ int   g_bsum[MAXB];                    // per-block degree sums

// ---------------------------------------------------------------------------
// helpers
// ---------------------------------------------------------------------------
__device__ __forceinline__ void tf32_split(float f, float& h, float& l) {
    unsigned hb;
    asm("cvt.rna.tf32.f32 %0, %1;" : "=r"(hb) : "f"(f));
    h = __uint_as_float(hb);
    float r = f - h;
    unsigned lb;
    asm("cvt.rna.tf32.f32 %0, %1;" : "=r"(lb) : "f"(r));
    l = __uint_as_float(lb);
}

__device__ __forceinline__ void mma_tf32(float* d, const float* a, const float* b) {
    asm volatile(
        "mma.sync.aligned.m16n8k8.row.col.f32.tf32.tf32.f32 "
        "{%0,%1,%2,%3}, {%4,%5,%6,%7}, {%8,%9}, {%0,%1,%2,%3};"
        : "+f"(d[0]), "+f"(d[1]), "+f"(d[2]), "+f"(d[3])
        : "r"(__float_as_uint(a[0])), "r"(__float_as_uint(a[1])),
          "r"(__float_as_uint(a[2])), "r"(__float_as_uint(a[3])),
          "r"(__float_as_uint(b[0])), "r"(__float_as_uint(b[1])));
}

__device__ __forceinline__ void cp16(unsigned saddr, const void* gaddr, int pred) {
    asm volatile("cp.async.cg.shared.global [%0], [%1], 16, %2;"
                 :: "r"(saddr), "l"(gaddr), "r"(pred ? 16 : 0));
}
__device__ __forceinline__ void cp_commit() { asm volatile("cp.async.commit_group;"); }
template <int N>
__device__ __forceinline__ void cp_wait() { asm volatile("cp.async.wait_group %0;" :: "n"(N)); }

// ---------------------------------------------------------------------------
// 1: fused mega-kernel: TC GEMM + logits epilogue + count blocks (REDG only)
// ---------------------------------------------------------------------------
#define AST 20     // A smem row stride (floats): conflict-free fragment loads
#define WST 136    // W smem row stride (floats): conflict-free fragment loads

__global__ __launch_bounds__(256)
void gemm_fused_kernel(const float* __restrict__ A, const float* __restrict__ W,
                       const float* __restrict__ a_dst, const float* __restrict__ b_dst,
                       const float* __restrict__ a_src, const float* __restrict__ b_src,
                       const int* __restrict__ edge_dst,
                       int n, int E, int gemm_blocks) {
    __shared__ float Ab[2][128 * AST];
    __shared__ float Wb[2][16 * WST];
    __shared__ float s_ed[128], s_es[128];

    const int tid = threadIdx.x;

    // ---------------- count path (fire-and-forget REDG) ----------------
    if ((int)blockIdx.x >= gemm_blocks) {
        const int stride = (gridDim.x - gemm_blocks) * 256;
        for (int e = (blockIdx.x - gemm_blocks) * 256 + tid; e < E; e += stride)
            atomicAdd(&g_deg[edge_dst[e]], 1);
        return;
    }

    // ---------------- GEMM path ----------------
    const int lane = tid & 31;
    const int wid  = tid >> 5;
    const int wm   = wid >> 2;         // 0..1
    const int wn   = wid & 3;          // 0..3
    const int block_row = blockIdx.x * 128;
    const int q  = lane >> 2;          // 0..7
    const int cc = lane & 3;           // 0..3

    const int ac0 = tid * 2;
    const int wc0 = tid * 2;

    const int   gr0  = block_row + (ac0 >> 2);
    const int   gr1  = block_row + ((ac0 + 1) >> 2);
    const float* gA0 = A + (size_t)gr0 * INDIM + ((ac0 & 3) * 4);
    const float* gA1 = A + (size_t)gr1 * INDIM + (((ac0 + 1) & 3) * 4);
    const int   p0   = gr0 < n;
    const int   p1   = gr1 < n;
    const float* gW0 = W + (size_t)(wc0 >> 5) * ODIM + ((wc0 & 31) * 4);
    const float* gW1 = W + (size_t)((wc0 + 1) >> 5) * ODIM + (((wc0 + 1) & 31) * 4);

    const unsigned sA0 = (unsigned)__cvta_generic_to_shared(&Ab[0][0])
                       + (unsigned)(((ac0 >> 2) * AST + (ac0 & 3) * 4) * 4);
    const unsigned sA1 = (unsigned)__cvta_generic_to_shared(&Ab[0][0])
                       + (unsigned)((((ac0 + 1) >> 2) * AST + ((ac0 + 1) & 3) * 4) * 4);
    const unsigned sW0 = (unsigned)__cvta_generic_to_shared(&Wb[0][0])
                       + (unsigned)(((wc0 >> 5) * WST + (wc0 & 31) * 4) * 4);
    const unsigned sW1 = (unsigned)__cvta_generic_to_shared(&Wb[0][0])
                       + (unsigned)((((wc0 + 1) >> 5) * WST + ((wc0 + 1) & 31) * 4) * 4);
    const unsigned abuf = 128 * AST * 4;
    const unsigned wbuf = 16 * WST * 4;

    auto issue = [&](int s, int buf) {
        cp16(sA0 + buf * abuf, gA0 + s * 16, p0);
        cp16(sA1 + buf * abuf, gA1 + s * 16, p1);
        cp16(sW0 + buf * wbuf, gW0 + (size_t)s * 16 * ODIM, 1);
        cp16(sW1 + buf * wbuf, gW1 + (size_t)s * 16 * ODIM, 1);
        cp_commit();
    };

    float acc[4][4][4];
#pragma unroll
    for (int mt = 0; mt < 4; mt++)
#pragma unroll
        for (int nt = 0; nt < 4; nt++)
#pragma unroll
            for (int j = 0; j < 4; j++) acc[mt][nt][j] = 0.f;

    issue(0, 0);

    const int NS = INDIM / 16;   // 16 slabs
    for (int s = 0; s < NS; s++) {
        const int buf = s & 1;
        if (s + 1 < NS) { issue(s + 1, buf ^ 1); cp_wait<1>(); }
        else            { cp_wait<0>(); }
        __syncthreads();

        const float* Ac = &Ab[buf][0];
        const float* Wc = &Wb[buf][0];

#pragma unroll
        for (int ks = 0; ks < 16; ks += 8) {
            float bh[4][2], bl[4][2];
#pragma unroll
            for (int nt = 0; nt < 4; nt++) {
                int col = wn * 32 + nt * 8 + q;
                float r0 = Wc[(ks + cc) * WST + col];
                float r1 = Wc[(ks + cc + 4) * WST + col];
                tf32_split(r0, bh[nt][0], bl[nt][0]);
                tf32_split(r1, bh[nt][1], bl[nt][1]);
            }
#pragma unroll
            for (int mt = 0; mt < 4; mt++) {
                int r = wm * 64 + mt * 16 + q;
                int c = ks + cc;
                float a0 = Ac[r * AST + c];
                float a1 = Ac[(r + 8) * AST + c];
                float a2 = Ac[r * AST + c + 4];
                float a3 = Ac[(r + 8) * AST + c + 4];
                float ah[4], al[4];
                tf32_split(a0, ah[0], al[0]);
                tf32_split(a1, ah[1], al[1]);
                tf32_split(a2, ah[2], al[2]);
                tf32_split(a3, ah[3], al[3]);
#pragma unroll
                for (int nt = 0; nt < 4; nt++) {
                    mma_tf32(acc[mt][nt], ah, bh[nt]);   // hi*hi
                    mma_tf32(acc[mt][nt], al, bh[nt]);   // lo*hi
                    mma_tf32(acc[mt][nt], ah, bl[nt]);   // hi*lo
                }
            }
        }
        __syncthreads();
    }

    // --- epilogue 1: store h' ---
#pragma unroll
    for (int mt = 0; mt < 4; mt++) {
#pragma unroll
        for (int nt = 0; nt < 4; nt++) {
            int row = block_row + wm * 64 + mt * 16 + q;
            int col = wn * 32 + nt * 8 + cc * 2;
            if (row < n)
                *(float2*)(g_h + (size_t)row * ODIM + col) =
                    make_float2(acc[mt][nt][0], acc[mt][nt][1]);
            if (row + 8 < n)
                *(float2*)(g_h + (size_t)(row + 8) * ODIM + col) =
                    make_float2(acc[mt][nt][2], acc[mt][nt][3]);
        }
    }

    // --- epilogue 2: fused logits e_dst/e_src ---
    if (tid < 128) { s_ed[tid] = 0.f; s_es[tid] = 0.f; }
    __syncthreads();
#pragma unroll
    for (int mt = 0; mt < 4; mt++) {
        float pd0 = 0.f, ps0 = 0.f, pd1 = 0.f, ps1 = 0.f;
#pragma unroll
        for (int nt = 0; nt < 4; nt++) {
            int col = wn * 32 + nt * 8 + cc * 2;
            float2 ad = *(const float2*)(a_dst + col);
            float2 as = *(const float2*)(a_src + col);
            pd0 += acc[mt][nt][0] * ad.x + acc[mt][nt][1] * ad.y;
            ps0 += acc[mt][nt][0] * as.x + acc[mt][nt][1] * as.y;
            pd1 += acc[mt][nt][2] * ad.x + acc[mt][nt][3] * ad.y;
            ps1 += acc[mt][nt][2] * as.x + acc[mt][nt][3] * as.y;
        }
#pragma unroll
        for (int o = 1; o < 4; o <<= 1) {
            pd0 += __shfl_xor_sync(0xffffffffu, pd0, o);
            ps0 += __shfl_xor_sync(0xffffffffu, ps0, o);
            pd1 += __shfl_xor_sync(0xffffffffu, pd1, o);
            ps1 += __shfl_xor_sync(0xffffffffu, ps1, o);
        }
        if (cc == 0) {
            int r0 = wm * 64 + mt * 16 + q;
            atomicAdd(&s_ed[r0], pd0);     atomicAdd(&s_es[r0], ps0);
            atomicAdd(&s_ed[r0 + 8], pd1); atomicAdd(&s_es[r0 + 8], ps1);
        }
    }
    __syncthreads();
    if (tid < 128) {
        int gr = block_row + tid;
        if (gr < n) {
            g_edst[gr] = s_ed[tid] + *b_dst;
            g_esrc[gr] = s_es[tid] + *b_src;
        }
    }
}

// ---------------------------------------------------------------------------
// 2: per-block local exclusive scan of g_deg -> g_row; re-zero g_deg
// ---------------------------------------------------------------------------
__global__ __launch_bounds__(SCAN_B)
void scanA_kernel(int n) {
    __shared__ int wsum[8];
    const int tid  = threadIdx.x;
    const int lane = tid & 31;
    const int w    = tid >> 5;
    const int i    = blockIdx.x * SCAN_B + tid;

    int v = 0;
    if (i < n) { v = g_deg[i]; g_deg[i] = 0; }   // restore zero invariant
    int incl = v;
#pragma unroll
    for (int o = 1; o < 32; o <<= 1) {
        int u = __shfl_up_sync(0xffffffffu, incl, o);
        if (lane >= o) incl += u;
    }
    if (lane == 31) wsum[w] = incl;
    __syncthreads();
    if (w == 0 && lane < 8) {
        int s = wsum[lane];
#pragma unroll
        for (int o = 1; o < 8; o <<= 1) {
            int u = __shfl_up_sync(0x000000ffu, s, o);
            if (lane >= o) s += u;
        }
        wsum[lane] = s;
    }
    __syncthreads();
    int excl = incl - v + (w > 0 ? wsum[w - 1] : 0);
    if (i < n) g_row[i] = excl;
    if (tid == 0) g_bsum[blockIdx.x] = wsum[7];
}

// ---------------------------------------------------------------------------
// 3: fused block-prefix + offset add + cursor init
// ---------------------------------------------------------------------------
__global__ __launch_bounds__(SCAN_B)
void scanBC_kernel(int nb, int n) {
    __shared__ int wsum[8];
    __shared__ int s_off, s_tot;
    const int tid  = threadIdx.x;
    const int lane = tid & 31;
    const int w    = tid >> 5;

    int v = (tid < nb) ? g_bsum[tid] : 0;
    int incl = v;
#pragma unroll
    for (int o = 1; o < 32; o <<= 1) {
        int u = __shfl_up_sync(0xffffffffu, incl, o);
        if (lane >= o) incl += u;
    }
    if (lane == 31) wsum[w] = incl;
    __syncthreads();
    if (w == 0 && lane < 8) {
        int s = wsum[lane];
#pragma unroll
        for (int o = 1; o < 8; o <<= 1) {
            int u = __shfl_up_sync(0x000000ffu, s, o);
            if (lane >= o) s += u;
        }
        wsum[lane] = s;
    }
    __syncthreads();
    if (tid == (int)blockIdx.x) s_off = incl - v + (w > 0 ? wsum[w - 1] : 0);
    if (tid == 0) s_tot = wsum[7];
    __syncthreads();

    const int i = blockIdx.x * SCAN_B + tid;
    if (i < n) {
        int r = g_row[i] + s_off;
        g_row[i] = r;
        g_cur[i] = r;
    }
    if (blockIdx.x == 0 && tid == 0) g_row[n] = s_tot;
}

// ---------------------------------------------------------------------------
// 4: bucket edges by destination; pack (leaky-score, src) into 8 bytes
// ---------------------------------------------------------------------------
__global__ void scatter_kernel(const int* __restrict__ edge_src,
                               const int* __restrict__ edge_dst, int E) {
    int e = blockIdx.x * blockDim.x + threadIdx.x;
    if (e < E) {
        int d = edge_dst[e];
        int s = edge_src[e];
        float sc = g_edst[d] + g_esrc[s];
        sc = sc >= 0.f ? sc : 0.2f * sc;
        int p = atomicAdd(&g_cur[d], 1);
        g_pack[p] = ((unsigned long long)__float_as_uint(sc) << 32) | (unsigned)s;
    }
}

// ---------------------------------------------------------------------------
// 5: per-dst online softmax + weighted aggregation, one warp per dst node.
//    Accumulate pass uses shuffle-broadcast: each lane computes alpha for its
//    own edge once; warp iterates the chunk broadcasting (alpha, src).
// ---------------------------------------------------------------------------
__global__ __launch_bounds__(256)
void agg_kernel(const float* __restrict__ out_bias,
                float* __restrict__ out, int n) {
    const int gw   = (blockIdx.x * blockDim.x + threadIdx.x) >> 5;
    const int lane = threadIdx.x & 31;
    if (gw >= n) return;

    const int beg = g_row[gw];
    const int end = g_row[gw + 1];

    // pass 1: online max + rescaled exp-sum (coalesced, lane-strided)
    float m = -INFINITY, ssum = 0.f;
    for (int i = beg + lane; i < end; i += 32) {
        float sc = __uint_as_float((unsigned)(g_pack[i] >> 32));
        if (sc > m) {
            ssum = ssum * __expf(m - sc) + 1.f;
            m = sc;
        } else {
            ssum += __expf(sc - m);
        }
    }
    float M = m;
#pragma unroll
    for (int o = 16; o; o >>= 1) M = fmaxf(M, __shfl_xor_sync(0xffffffffu, M, o));
    float part = (m == -INFINITY) ? 0.f : ssum * __expf(m - M);
#pragma unroll
    for (int o = 16; o; o >>= 1) part += __shfl_xor_sync(0xffffffffu, part, o);
    const float inv = 1.f / fmaxf(part, 1e-12f);

    // pass 2: weighted gather; alpha computed once per edge, shuffled to warp
    const int c = lane * 4;
    float a0 = 0.f, a1 = 0.f, a2 = 0.f, a3 = 0.f;
    for (int i0 = beg; i0 < end; i0 += 32) {
        int i = i0 + lane;
        float al = 0.f;
        int   s  = 0;
        if (i < end) {
            unsigned long long pk = g_pack[i];
            s  = (int)(unsigned)pk;
            al = __expf(__uint_as_float((unsigned)(pk >> 32)) - M) * inv;
        }
        const int cnt = min(32, end - i0);
        for (int j = 0; j < cnt; j++) {
            float a  = __shfl_sync(0xffffffffu, al, j);
            int   ss = __shfl_sync(0xffffffffu, s,  j);
            float4 v = *(const float4*)(g_h + (size_t)ss * ODIM + c);
            a0 += a * v.x; a1 += a * v.y; a2 += a * v.z; a3 += a * v.w;
        }
    }

    float4 b4 = *(const float4*)(out_bias + c);
    a0 += b4.x; a1 += b4.y; a2 += b4.z; a3 += b4.w;
    float4 o4;
    o4.x = a0 > 0.f ? a0 : expm1f(a0);
    o4.y = a1 > 0.f ? a1 : expm1f(a1);
    o4.z = a2 > 0.f ? a2 : expm1f(a2);
    o4.w = a3 > 0.f ? a3 : expm1f(a3);
    *(float4*)(out + (size_t)gw * ODIM + c) = o4;
}

// ---------------------------------------------------------------------------
extern "C" void kernel_launch(void* const* d_in, const int* in_sizes, int n_in,
                              void* d_out, int out_size) {
    const float* inputs   = (const float*)d_in[0];
    const int*   edge_src = (const int*)d_in[1];
    const int*   edge_dst = (const int*)d_in[2];
    const float* W_seq    = (const float*)d_in[3];
    const float* a_dst    = (const float*)d_in[4];
    const float* b_dst    = (const float*)d_in[5];
    const float* a_src    = (const float*)d_in[6];
    const float* b_src    = (const float*)d_in[7];
    const float* out_bias = (const float*)d_in[8];
    float* out = (float*)d_out;

    const int n = in_sizes[0] / INDIM;
    const int E = in_sizes[1];
    const int nb = (n + SCAN_B - 1) / SCAN_B;
    const int gemm_blocks = (n + 127) / 128;
    const int cnt_blocks  = 1024;

    gemm_fused_kernel<<<gemm_blocks + cnt_blocks, 256>>>(
        inputs, W_seq, a_dst, b_dst, a_src, b_src, edge_dst, n, E, gemm_blocks);
    scanA_kernel<<<nb, SCAN_B>>>(n);
    scanBC_kernel<<<nb, SCAN_B>>>(nb, n);
    scatter_kernel<<<(E + 255) / 256, 256>>>(edge_src, edge_dst, E);
    agg_kernel<<<(n * 32 + 255) / 256, 256>>>(out_bias, out, n);
}

// round 11
// speedup vs baseline: 1.2846x; 1.1387x over previous
#include <cuda_runtime.h>
#include <cuda_fp16.h>
#include <math.h>

// Problem constants (fixed by the dataset)
#define MAXN 50048
#define MAXE 800000
#define INDIM 256
#define ODIM 128
#define SCAN_B 256
#define MAXB ((MAXN + SCAN_B - 1) / SCAN_B)

// Scratch (device globals; no allocation allowed)
__device__ __half2 g_hb[(size_t)MAXN * (ODIM / 2)];  // h_prime in fp16 [N,128]
__device__ float g_edst[MAXN];                    // e_dst per node (incl bias)
__device__ float g_esrc[MAXN];                    // e_src per node (incl bias)
__device__ int   g_deg[MAXN];                     // in-degree (zero at load; scanA re-zeroes)
__device__ int   g_row[MAXN + 1];                 // CSR row offsets
__device__ int   g_cur[MAXN];                     // scatter cursors
__device__ unsigned long long g_pack[MAXE];       // packed (score<<32 | src) per bucketed edge
__device__ int   g_bsum[MAXB];                    // per-block degree sums

// ---------------------------------------------------------------------------
// helpers
// ---------------------------------------------------------------------------
__device__ __forceinline__ void tf32_split(float f, float& h, float& l) {
    unsigned hb;
    asm("cvt.rna.tf32.f32 %0, %1;" : "=r"(hb) : "f"(f));
    h = __uint_as_float(hb);
    float r = f - h;
    unsigned lb;
    asm("cvt.rna.tf32.f32 %0, %1;" : "=r"(lb) : "f"(r));
    l = __uint_as_float(lb);
}

__device__ __forceinline__ void mma_tf32(float* d, const float* a, const float* b) {
    asm volatile(
        "mma.sync.aligned.m16n8k8.row.col.f32.tf32.tf32.f32 "
        "{%0,%1,%2,%3}, {%4,%5,%6,%7}, {%8,%9}, {%0,%1,%2,%3};"
        : "+f"(d[0]), "+f"(d[1]), "+f"(d[2]), "+f"(d[3])
        : "r"(__float_as_uint(a[0])), "r"(__float_as_uint(a[1])),
          "r"(__float_as_uint(a[2])), "r"(__float_as_uint(a[3])),
          "r"(__float_as_uint(b[0])), "r"(__float_as_uint(b[1])));
}

__device__ __forceinline__ void cp16(unsigned saddr, const void* gaddr, int pred) {
    asm volatile("cp.async.cg.shared.global [%0], [%1], 16, %2;"
                 :: "r"(saddr), "l"(gaddr), "r"(pred ? 16 : 0));
}
__device__ __forceinline__ void cp_commit() { asm volatile("cp.async.commit_group;"); }
template <int N>
__device__ __forceinline__ void cp_wait() { asm volatile("cp.async.wait_group %0;" :: "n"(N)); }

// ---------------------------------------------------------------------------
// 1: fused mega-kernel: TC GEMM + logits epilogue + count blocks (REDG only)
// ---------------------------------------------------------------------------
#define AST 20     // A smem row stride (floats): conflict-free fragment loads
#define WST 136    // W smem row stride (floats): conflict-free fragment loads

__global__ __launch_bounds__(256)
void gemm_fused_kernel(const float* __restrict__ A, const float* __restrict__ W,
                       const float* __restrict__ a_dst, const float* __restrict__ b_dst,
                       const float* __restrict__ a_src, const float* __restrict__ b_src,
                       const int* __restrict__ edge_dst,
                       int n, int E, int gemm_blocks) {
    __shared__ float Ab[2][128 * AST];
    __shared__ float Wb[2][16 * WST];
    __shared__ float s_ed[128], s_es[128];

    const int tid = threadIdx.x;

    // ---------------- count path (fire-and-forget REDG) ----------------
    if ((int)blockIdx.x >= gemm_blocks) {
        const int stride = (gridDim.x - gemm_blocks) * 256;
        for (int e = (blockIdx.x - gemm_blocks) * 256 + tid; e < E; e += stride)
            atomicAdd(&g_deg[edge_dst[e]], 1);
        return;
    }

    // ---------------- GEMM path ----------------
    const int lane = tid & 31;
    const int wid  = tid >> 5;
    const int wm   = wid >> 2;         // 0..1
    const int wn   = wid & 3;          // 0..3
    const int block_row = blockIdx.x * 128;
    const int q  = lane >> 2;          // 0..7
    const int cc = lane & 3;           // 0..3

    const int ac0 = tid * 2;
    const int wc0 = tid * 2;

    const int   gr0  = block_row + (ac0 >> 2);
    const int   gr1  = block_row + ((ac0 + 1) >> 2);
    const float* gA0 = A + (size_t)gr0 * INDIM + ((ac0 & 3) * 4);
    const float* gA1 = A + (size_t)gr1 * INDIM + (((ac0 + 1) & 3) * 4);
    const int   p0   = gr0 < n;
    const int   p1   = gr1 < n;
    const float* gW0 = W + (size_t)(wc0 >> 5) * ODIM + ((wc0 & 31) * 4);
    const float* gW1 = W + (size_t)((wc0 + 1) >> 5) * ODIM + (((wc0 + 1) & 31) * 4);

    const unsigned sA0 = (unsigned)__cvta_generic_to_shared(&Ab[0][0])
                       + (unsigned)(((ac0 >> 2) * AST + (ac0 & 3) * 4) * 4);
    const unsigned sA1 = (unsigned)__cvta_generic_to_shared(&Ab[0][0])
                       + (unsigned)((((ac0 + 1) >> 2) * AST + ((ac0 + 1) & 3) * 4) * 4);
    const unsigned sW0 = (unsigned)__cvta_generic_to_shared(&Wb[0][0])
                       + (unsigned)(((wc0 >> 5) * WST + (wc0 & 31) * 4) * 4);
    const unsigned sW1 = (unsigned)__cvta_generic_to_shared(&Wb[0][0])
                       + (unsigned)((((wc0 + 1) >> 5) * WST + ((wc0 + 1) & 31) * 4) * 4);
    const unsigned abuf = 128 * AST * 4;
    const unsigned wbuf = 16 * WST * 4;

    auto issue = [&](int s, int buf) {
        cp16(sA0 + buf * abuf, gA0 + s * 16, p0);
        cp16(sA1 + buf * abuf, gA1 + s * 16, p1);
        cp16(sW0 + buf * wbuf, gW0 + (size_t)s * 16 * ODIM, 1);
        cp16(sW1 + buf * wbuf, gW1 + (size_t)s * 16 * ODIM, 1);
        cp_commit();
    };

    float acc[4][4][4];
#pragma unroll
    for (int mt = 0; mt < 4; mt++)
#pragma unroll
        for (int nt = 0; nt < 4; nt++)
#pragma unroll
            for (int j = 0; j < 4; j++) acc[mt][nt][j] = 0.f;

    issue(0, 0);

    const int NS = INDIM / 16;   // 16 slabs
    for (int s = 0; s < NS; s++) {
        const int buf = s & 1;
        if (s + 1 < NS) { issue(s + 1, buf ^ 1); cp_wait<1>(); }
        else            { cp_wait<0>(); }
        __syncthreads();

        const float* Ac = &Ab[buf][0];
        const float* Wc = &Wb[buf][0];

#pragma unroll
        for (int ks = 0; ks < 16; ks += 8) {
            float bh[4][2], bl[4][2];
#pragma unroll
            for (int nt = 0; nt < 4; nt++) {
                int col = wn * 32 + nt * 8 + q;
                float r0 = Wc[(ks + cc) * WST + col];
                float r1 = Wc[(ks + cc + 4) * WST + col];
                tf32_split(r0, bh[nt][0], bl[nt][0]);
                tf32_split(r1, bh[nt][1], bl[nt][1]);
            }
#pragma unroll
            for (int mt = 0; mt < 4; mt++) {
                int r = wm * 64 + mt * 16 + q;
                int c = ks + cc;
                float a0 = Ac[r * AST + c];
                float a1 = Ac[(r + 8) * AST + c];
                float a2 = Ac[r * AST + c + 4];
                float a3 = Ac[(r + 8) * AST + c + 4];
                float ah[4], al[4];
                tf32_split(a0, ah[0], al[0]);
                tf32_split(a1, ah[1], al[1]);
                tf32_split(a2, ah[2], al[2]);
                tf32_split(a3, ah[3], al[3]);
#pragma unroll
                for (int nt = 0; nt < 4; nt++) {
                    mma_tf32(acc[mt][nt], ah, bh[nt]);   // hi*hi
                    mma_tf32(acc[mt][nt], al, bh[nt]);   // lo*hi
                    mma_tf32(acc[mt][nt], ah, bl[nt]);   // hi*lo
                }
            }
        }
        __syncthreads();
    }

    // --- epilogue 1: store h' as fp16 (only consumer is the gather) ---
#pragma unroll
    for (int mt = 0; mt < 4; mt++) {
#pragma unroll
        for (int nt = 0; nt < 4; nt++) {
            int row = block_row + wm * 64 + mt * 16 + q;
            int hcol = wn * 16 + nt * 4 + cc;          // half2 column index
            if (row < n)
                g_hb[(size_t)row * 64 + hcol] = __floats2half2_rn(acc[mt][nt][0], acc[mt][nt][1]);
            if (row + 8 < n)
                g_hb[(size_t)(row + 8) * 64 + hcol] = __floats2half2_rn(acc[mt][nt][2], acc[mt][nt][3]);
        }
    }

    // --- epilogue 2: fused logits e_dst/e_src (fp32 accumulators) ---
    if (tid < 128) { s_ed[tid] = 0.f; s_es[tid] = 0.f; }
    __syncthreads();
#pragma unroll
    for (int mt = 0; mt < 4; mt++) {
        float pd0 = 0.f, ps0 = 0.f, pd1 = 0.f, ps1 = 0.f;
#pragma unroll
        for (int nt = 0; nt < 4; nt++) {
            int col = wn * 32 + nt * 8 + cc * 2;
            float2 ad = *(const float2*)(a_dst + col);
            float2 as = *(const float2*)(a_src + col);
            pd0 += acc[mt][nt][0] * ad.x + acc[mt][nt][1] * ad.y;
            ps0 += acc[mt][nt][0] * as.x + acc[mt][nt][1] * as.y;
            pd1 += acc[mt][nt][2] * ad.x + acc[mt][nt][3] * ad.y;
            ps1 += acc[mt][nt][2] * as.x + acc[mt][nt][3] * as.y;
        }
#pragma unroll
        for (int o = 1; o < 4; o <<= 1) {
            pd0 += __shfl_xor_sync(0xffffffffu, pd0, o);
            ps0 += __shfl_xor_sync(0xffffffffu, ps0, o);
            pd1 += __shfl_xor_sync(0xffffffffu, pd1, o);
            ps1 += __shfl_xor_sync(0xffffffffu, ps1, o);
        }
        if (cc == 0) {
            int r0 = wm * 64 + mt * 16 + q;
            atomicAdd(&s_ed[r0], pd0);     atomicAdd(&s_es[r0], ps0);
            atomicAdd(&s_ed[r0 + 8], pd1); atomicAdd(&s_es[r0 + 8], ps1);
        }
    }
    __syncthreads();
    if (tid < 128) {
        int gr = block_row + tid;
        if (gr < n) {
            g_edst[gr] = s_ed[tid] + *b_dst;
            g_esrc[gr] = s_es[tid] + *b_src;
        }
    }
}

// ---------------------------------------------------------------------------
// 2: per-block local exclusive scan of g_deg -> g_row; re-zero g_deg
// ---------------------------------------------------------------------------
__global__ __launch_bounds__(SCAN_B)
void scanA_kernel(int n) {
    __shared__ int wsum[8];
    const int tid  = threadIdx.x;
    const int lane = tid & 31;
    const int w    = tid >> 5;
    const int i    = blockIdx.x * SCAN_B + tid;

    int v = 0;
    if (i < n) { v = g_deg[i]; g_deg[i] = 0; }   // restore zero invariant
    int incl = v;
#pragma unroll
    for (int o = 1; o < 32; o <<= 1) {
        int u = __shfl_up_sync(0xffffffffu, incl, o);
        if (lane >= o) incl += u;
    }
    if (lane == 31) wsum[w] = incl;
    __syncthreads();
    if (w == 0 && lane < 8) {
        int s = wsum[lane];
#pragma unroll
        for (int o = 1; o < 8; o <<= 1) {
            int u = __shfl_up_sync(0x000000ffu, s, o);
            if (lane >= o) s += u;
        }
        wsum[lane] = s;
    }
    __syncthreads();
    int excl = incl - v + (w > 0 ? wsum[w - 1] : 0);
    if (i < n) g_row[i] = excl;
    if (tid == 0) g_bsum[blockIdx.x] = wsum[7];
}

// ---------------------------------------------------------------------------
// 3: fused block-prefix + offset add + cursor init
// ---------------------------------------------------------------------------
__global__ __launch_bounds__(SCAN_B)
void scanBC_kernel(int nb, int n) {
    __shared__ int wsum[8];
    __shared__ int s_off, s_tot;
    const int tid  = threadIdx.x;
    const int lane = tid & 31;
    const int w    = tid >> 5;

    int v = (tid < nb) ? g_bsum[tid] : 0;
    int incl = v;
#pragma unroll
    for (int o = 1; o < 32; o <<= 1) {
        int u = __shfl_up_sync(0xffffffffu, incl, o);
        if (lane >= o) incl += u;
    }
    if (lane == 31) wsum[w] = incl;
    __syncthreads();
    if (w == 0 && lane < 8) {
        int s = wsum[lane];
#pragma unroll
        for (int o = 1; o < 8; o <<= 1) {
            int u = __shfl_up_sync(0x000000ffu, s, o);
            if (lane >= o) s += u;
        }
        wsum[lane] = s;
    }
    __syncthreads();
    if (tid == (int)blockIdx.x) s_off = incl - v + (w > 0 ? wsum[w - 1] : 0);
    if (tid == 0) s_tot = wsum[7];
    __syncthreads();

    const int i = blockIdx.x * SCAN_B + tid;
    if (i < n) {
        int r = g_row[i] + s_off;
        g_row[i] = r;
        g_cur[i] = r;
    }
    if (blockIdx.x == 0 && tid == 0) g_row[n] = s_tot;
}

// ---------------------------------------------------------------------------
// 4: bucket edges; 4 edges per thread for memory-level parallelism
// ---------------------------------------------------------------------------
__global__ void scatter_kernel(const int* __restrict__ edge_src,
                               const int* __restrict__ edge_dst, int E) {
    const int base = (blockIdx.x * blockDim.x + threadIdx.x) * 4;
    if (base + 3 < E) {
        const int4 d4 = *(const int4*)(edge_dst + base);
        const int4 s4 = *(const int4*)(edge_src + base);
        // 4 independent L2 lookups each — MLP hides latency
        float ed0 = g_edst[d4.x], ed1 = g_edst[d4.y], ed2 = g_edst[d4.z], ed3 = g_edst[d4.w];
        float es0 = g_esrc[s4.x], es1 = g_esrc[s4.y], es2 = g_esrc[s4.z], es3 = g_esrc[s4.w];
        float c0 = ed0 + es0; c0 = c0 >= 0.f ? c0 : 0.2f * c0;
        float c1 = ed1 + es1; c1 = c1 >= 0.f ? c1 : 0.2f * c1;
        float c2 = ed2 + es2; c2 = c2 >= 0.f ? c2 : 0.2f * c2;
        float c3 = ed3 + es3; c3 = c3 >= 0.f ? c3 : 0.2f * c3;
        int q0 = atomicAdd(&g_cur[d4.x], 1);
        int q1 = atomicAdd(&g_cur[d4.y], 1);
        int q2 = atomicAdd(&g_cur[d4.z], 1);
        int q3 = atomicAdd(&g_cur[d4.w], 1);
        g_pack[q0] = ((unsigned long long)__float_as_uint(c0) << 32) | (unsigned)s4.x;
        g_pack[q1] = ((unsigned long long)__float_as_uint(c1) << 32) | (unsigned)s4.y;
        g_pack[q2] = ((unsigned long long)__float_as_uint(c2) << 32) | (unsigned)s4.z;
        g_pack[q3] = ((unsigned long long)__float_as_uint(c3) << 32) | (unsigned)s4.w;
    } else {
        for (int e = base; e < E; e++) {
            int d = edge_dst[e];
            int s = edge_src[e];
            float sc = g_edst[d] + g_esrc[s];
            sc = sc >= 0.f ? sc : 0.2f * sc;
            int p = atomicAdd(&g_cur[d], 1);
            g_pack[p] = ((unsigned long long)__float_as_uint(sc) << 32) | (unsigned)s;
        }
    }
}

// ---------------------------------------------------------------------------
// 5: per-dst online softmax + weighted aggregation (fp16 gather, fp32 math)
// ---------------------------------------------------------------------------
__global__ __launch_bounds__(256)
void agg_kernel(const float* __restrict__ out_bias,
                float* __restrict__ out, int n) {
    const int gw   = (blockIdx.x * blockDim.x + threadIdx.x) >> 5;
    const int lane = threadIdx.x & 31;
    if (gw >= n) return;

    const int beg = g_row[gw];
    const int end = g_row[gw + 1];

    // pass 1: online max + rescaled exp-sum (coalesced, lane-strided, fp32)
    float m = -INFINITY, ssum = 0.f;
    for (int i = beg + lane; i < end; i += 32) {
        float sc = __uint_as_float((unsigned)(g_pack[i] >> 32));
        if (sc > m) {
            ssum = ssum * __expf(m - sc) + 1.f;
            m = sc;
        } else {
            ssum += __expf(sc - m);
        }
    }
    float M = m;
#pragma unroll
    for (int o = 16; o; o >>= 1) M = fmaxf(M, __shfl_xor_sync(0xffffffffu, M, o));
    float part = (m == -INFINITY) ? 0.f : ssum * __expf(m - M);
#pragma unroll
    for (int o = 16; o; o >>= 1) part += __shfl_xor_sync(0xffffffffu, part, o);
    const float inv = 1.f / fmaxf(part, 1e-12f);

    // pass 2: weighted gather from fp16 h' (256B/edge), fp32 accumulate
    const int hcol = lane * 2;   // half2 col index (covers 4 halves per lane)
    float a0 = 0.f, a1 = 0.f, a2 = 0.f, a3 = 0.f;
    for (int i = beg; i < end; i++) {
        unsigned long long pk = g_pack[i];
        int s = (int)(unsigned)pk;
        float al = __expf(__uint_as_float((unsigned)(pk >> 32)) - M) * inv;
        uint2 u = *(const uint2*)(g_hb + (size_t)s * 64 + hcol);
        float2 f01 = __half22float2(*(__half2*)&u.x);
        float2 f23 = __half22float2(*(__half2*)&u.y);
        a0 += al * f01.x; a1 += al * f01.y; a2 += al * f23.x; a3 += al * f23.y;
    }

    const int c = lane * 4;
    float4 b4 = *(const float4*)(out_bias + c);
    a0 += b4.x; a1 += b4.y; a2 += b4.z; a3 += b4.w;
    float4 o4;
    o4.x = a0 > 0.f ? a0 : expm1f(a0);
    o4.y = a1 > 0.f ? a1 : expm1f(a1);
    o4.z = a2 > 0.f ? a2 : expm1f(a2);
    o4.w = a3 > 0.f ? a3 : expm1f(a3);
    *(float4*)(out + (size_t)gw * ODIM + c) = o4;
}

// ---------------------------------------------------------------------------
extern "C" void kernel_launch(void* const* d_in, const int* in_sizes, int n_in,
                              void* d_out, int out_size) {
    const float* inputs   = (const float*)d_in[0];
    const int*   edge_src = (const int*)d_in[1];
    const int*   edge_dst = (const int*)d_in[2];
    const float* W_seq    = (const float*)d_in[3];
    const float* a_dst    = (const float*)d_in[4];
    const float* b_dst    = (const float*)d_in[5];
    const float* a_src    = (const float*)d_in[6];
    const float* b_src    = (const float*)d_in[7];
    const float* out_bias = (const float*)d_in[8];
    float* out = (float*)d_out;

    const int n = in_sizes[0] / INDIM;
    const int E = in_sizes[1];
    const int nb = (n + SCAN_B - 1) / SCAN_B;
    const int gemm_blocks = (n + 127) / 128;
    const int cnt_blocks  = 1024;

    gemm_fused_kernel<<<gemm_blocks + cnt_blocks, 256>>>(
        inputs, W_seq, a_dst, b_dst, a_src, b_src, edge_dst, n, E, gemm_blocks);
    scanA_kernel<<<nb, SCAN_B>>>(n);
    scanBC_kernel<<<nb, SCAN_B>>>(nb, n);
    scatter_kernel<<<(E / 4 + 255) / 256, 256>>>(edge_src, edge_dst, E);
    agg_kernel<<<(n * 32 + 255) / 256, 256>>>(out_bias, out, n);
}

// round 15
// speedup vs baseline: 1.4614x; 1.1376x over previous
#include <cuda_runtime.h>
#include <cuda_fp16.h>
#include <math.h>

// Problem constants (fixed by the dataset)
#define MAXN 50048
#define MAXE 800000
#define INDIM 256
#define ODIM 128
#define SCAN_B 256
#define MAXB ((MAXN + SCAN_B - 1) / SCAN_B)

// Scratch (device globals; no allocation allowed)
__device__ __half2 g_hb[(size_t)MAXN * (ODIM / 2)];  // h_prime in fp16 [N,128]
__device__ float g_edst[MAXN];                    // e_dst per node (incl bias)
__device__ float g_esrc[MAXN];                    // e_src per node (incl bias)
__device__ int   g_deg[MAXN];                     // in-degree (zero at load; scanA re-zeroes)
__device__ int   g_row[MAXN + 1];                 // CSR row offsets
__device__ int   g_cur[MAXN];                     // scatter cursors
__device__ unsigned long long g_pack[MAXE];       // packed (score<<32 | src) per bucketed edge
__device__ int   g_bsum[MAXB];                    // per-block degree sums

// ---------------------------------------------------------------------------
// helpers
// ---------------------------------------------------------------------------
__device__ __forceinline__ float to_tf32(float f) {
    unsigned b;
    asm("cvt.rna.tf32.f32 %0, %1;" : "=r"(b) : "f"(f));
    return __uint_as_float(b);
}

__device__ __forceinline__ void tf32_split(float f, float& h, float& l) {
    h = to_tf32(f);
    l = to_tf32(f - h);
}

__device__ __forceinline__ void mma_tf32(float* d, const float* a, const float* b) {
    asm volatile(
        "mma.sync.aligned.m16n8k8.row.col.f32.tf32.tf32.f32 "
        "{%0,%1,%2,%3}, {%4,%5,%6,%7}, {%8,%9}, {%0,%1,%2,%3};"
        : "+f"(d[0]), "+f"(d[1]), "+f"(d[2]), "+f"(d[3])
        : "r"(__float_as_uint(a[0])), "r"(__float_as_uint(a[1])),
          "r"(__float_as_uint(a[2])), "r"(__float_as_uint(a[3])),
          "r"(__float_as_uint(b[0])), "r"(__float_as_uint(b[1])));
}

__device__ __forceinline__ void cp16(unsigned saddr, const void* gaddr, int pred) {
    asm volatile("cp.async.cg.shared.global [%0], [%1], 16, %2;"
                 :: "r"(saddr), "l"(gaddr), "r"(pred ? 16 : 0));
}
__device__ __forceinline__ void cp_commit() { asm volatile("cp.async.commit_group;"); }
template <int N>
__device__ __forceinline__ void cp_wait() { asm volatile("cp.async.wait_group %0;" :: "n"(N)); }

// ---------------------------------------------------------------------------
// 1: fused mega-kernel: TC GEMM (2-term TF32: A_tf32 x (W_hi + W_lo))
//    + logits epilogue + count blocks (REDG only)
// ---------------------------------------------------------------------------
#define AST 20     // A smem row stride (floats): conflict-free fragment loads
#define WST 136    // W smem row stride (floats): conflict-free fragment loads

__global__ __launch_bounds__(256)
void gemm_fused_kernel(const float* __restrict__ A, const float* __restrict__ W,
                       const float* __restrict__ a_dst, const float* __restrict__ b_dst,
                       const float* __restrict__ a_src, const float* __restrict__ b_src,
                       const int* __restrict__ edge_dst,
                       int n, int E, int gemm_blocks) {
    __shared__ float Ab[2][128 * AST];
    __shared__ float Wb[2][16 * WST];
    __shared__ float s_ed[128], s_es[128];

    const int tid = threadIdx.x;

    // ---------------- count path (fire-and-forget REDG) ----------------
    if ((int)blockIdx.x >= gemm_blocks) {
        const int stride = (gridDim.x - gemm_blocks) * 256;
        for (int e = (blockIdx.x - gemm_blocks) * 256 + tid; e < E; e += stride)
            atomicAdd(&g_deg[edge_dst[e]], 1);
        return;
    }

    // ---------------- GEMM path ----------------
    const int lane = tid & 31;
    const int wid  = tid >> 5;
    const int wm   = wid >> 2;         // 0..1
    const int wn   = wid & 3;          // 0..3
    const int block_row = blockIdx.x * 128;
    const int q  = lane >> 2;          // 0..7
    const int cc = lane & 3;           // 0..3

    const int ac0 = tid * 2;
    const int wc0 = tid * 2;

    const int   gr0  = block_row + (ac0 >> 2);
    const int   gr1  = block_row + ((ac0 + 1) >> 2);
    const float* gA0 = A + (size_t)gr0 * INDIM + ((ac0 & 3) * 4);
    const float* gA1 = A + (size_t)gr1 * INDIM + (((ac0 + 1) & 3) * 4);
    const int   p0   = gr0 < n;
    const int   p1   = gr1 < n;
    const float* gW0 = W + (size_t)(wc0 >> 5) * ODIM + ((wc0 & 31) * 4);
    const float* gW1 = W + (size_t)((wc0 + 1) >> 5) * ODIM + (((wc0 + 1) & 31) * 4);

    const unsigned sA0 = (unsigned)__cvta_generic_to_shared(&Ab[0][0])
                       + (unsigned)(((ac0 >> 2) * AST + (ac0 & 3) * 4) * 4);
    const unsigned sA1 = (unsigned)__cvta_generic_to_shared(&Ab[0][0])
                       + (unsigned)((((ac0 + 1) >> 2) * AST + ((ac0 + 1) & 3) * 4) * 4);
    const unsigned sW0 = (unsigned)__cvta_generic_to_shared(&Wb[0][0])
                       + (unsigned)(((wc0 >> 5) * WST + (wc0 & 31) * 4) * 4);
    const unsigned sW1 = (unsigned)__cvta_generic_to_shared(&Wb[0][0])
                       + (unsigned)((((wc0 + 1) >> 5) * WST + ((wc0 + 1) & 31) * 4) * 4);
    const unsigned abuf = 128 * AST * 4;
    const unsigned wbuf = 16 * WST * 4;

    auto issue = [&](int s, int buf) {
        cp16(sA0 + buf * abuf, gA0 + s * 16, p0);
        cp16(sA1 + buf * abuf, gA1 + s * 16, p1);
        cp16(sW0 + buf * wbuf, gW0 + (size_t)s * 16 * ODIM, 1);
        cp16(sW1 + buf * wbuf, gW1 + (size_t)s * 16 * ODIM, 1);
        cp_commit();
    };

    float acc[4][4][4];
#pragma unroll
    for (int mt = 0; mt < 4; mt++)
#pragma unroll
        for (int nt = 0; nt < 4; nt++)
#pragma unroll
            for (int j = 0; j < 4; j++) acc[mt][nt][j] = 0.f;

    issue(0, 0);

    const int NS = INDIM / 16;   // 16 slabs
    for (int s = 0; s < NS; s++) {
        const int buf = s & 1;
        if (s + 1 < NS) { issue(s + 1, buf ^ 1); cp_wait<1>(); }
        else            { cp_wait<0>(); }
        __syncthreads();

        const float* Ac = &Ab[buf][0];
        const float* Wc = &Wb[buf][0];

#pragma unroll
        for (int ks = 0; ks < 16; ks += 8) {
            // B fragments: split into hi + lo (W fully compensated)
            float bh[4][2], bl[4][2];
#pragma unroll
            for (int nt = 0; nt < 4; nt++) {
                int col = wn * 32 + nt * 8 + q;
                float r0 = Wc[(ks + cc) * WST + col];
                float r1 = Wc[(ks + cc + 4) * WST + col];
                tf32_split(r0, bh[nt][0], bl[nt][0]);
                tf32_split(r1, bh[nt][1], bl[nt][1]);
            }
#pragma unroll
            for (int mt = 0; mt < 4; mt++) {
                int r = wm * 64 + mt * 16 + q;
                int c = ks + cc;
                // A fragments: single tf32 (one rounding, ~2e-4 RMS)
                float ah[4];
                ah[0] = to_tf32(Ac[r * AST + c]);
                ah[1] = to_tf32(Ac[(r + 8) * AST + c]);
                ah[2] = to_tf32(Ac[r * AST + c + 4]);
                ah[3] = to_tf32(Ac[(r + 8) * AST + c + 4]);
#pragma unroll
                for (int nt = 0; nt < 4; nt++) {
                    mma_tf32(acc[mt][nt], ah, bh[nt]);   // A*W_hi
                    mma_tf32(acc[mt][nt], ah, bl[nt]);   // A*W_lo
                }
            }
        }
        __syncthreads();
    }

    // --- epilogue 1: store h' as fp16 (only consumer is the gather) ---
#pragma unroll
    for (int mt = 0; mt < 4; mt++) {
#pragma unroll
        for (int nt = 0; nt < 4; nt++) {
            int row = block_row + wm * 64 + mt * 16 + q;
            int hcol = wn * 16 + nt * 4 + cc;          // half2 column index
            if (row < n)
                g_hb[(size_t)row * 64 + hcol] = __floats2half2_rn(acc[mt][nt][0], acc[mt][nt][1]);
            if (row + 8 < n)
                g_hb[(size_t)(row + 8) * 64 + hcol] = __floats2half2_rn(acc[mt][nt][2], acc[mt][nt][3]);
        }
    }

    // --- epilogue 2: fused logits e_dst/e_src (fp32 accumulators) ---
    if (tid < 128) { s_ed[tid] = 0.f; s_es[tid] = 0.f; }
    __syncthreads();
#pragma unroll
    for (int mt = 0; mt < 4; mt++) {
        float pd0 = 0.f, ps0 = 0.f, pd1 = 0.f, ps1 = 0.f;
#pragma unroll
        for (int nt = 0; nt < 4; nt++) {
            int col = wn * 32 + nt * 8 + cc * 2;
            float2 ad = *(const float2*)(a_dst + col);
            float2 as = *(const float2*)(a_src + col);
            pd0 += acc[mt][nt][0] * ad.x + acc[mt][nt][1] * ad.y;
            ps0 += acc[mt][nt][0] * as.x + acc[mt][nt][1] * as.y;
            pd1 += acc[mt][nt][2] * ad.x + acc[mt][nt][3] * ad.y;
            ps1 += acc[mt][nt][2] * as.x + acc[mt][nt][3] * as.y;
        }
#pragma unroll
        for (int o = 1; o < 4; o <<= 1) {
            pd0 += __shfl_xor_sync(0xffffffffu, pd0, o);
            ps0 += __shfl_xor_sync(0xffffffffu, ps0, o);
            pd1 += __shfl_xor_sync(0xffffffffu, pd1, o);
            ps1 += __shfl_xor_sync(0xffffffffu, ps1, o);
        }
        if (cc == 0) {
            int r0 = wm * 64 + mt * 16 + q;
            atomicAdd(&s_ed[r0], pd0);     atomicAdd(&s_es[r0], ps0);
            atomicAdd(&s_ed[r0 + 8], pd1); atomicAdd(&s_es[r0 + 8], ps1);
        }
    }
    __syncthreads();
    if (tid < 128) {
        int gr = block_row + tid;
        if (gr < n) {
            g_edst[gr] = s_ed[tid] + *b_dst;
            g_esrc[gr] = s_es[tid] + *b_src;
        }
    }
}

// ---------------------------------------------------------------------------
// 2: per-block local exclusive scan of g_deg -> g_row; re-zero g_deg
// ---------------------------------------------------------------------------
__global__ __launch_bounds__(SCAN_B)
void scanA_kernel(int n) {
    __shared__ int wsum[8];
    const int tid  = threadIdx.x;
    const int lane = tid & 31;
    const int w    = tid >> 5;
    const int i    = blockIdx.x * SCAN_B + tid;

    int v = 0;
    if (i < n) { v = g_deg[i]; g_deg[i] = 0; }   // restore zero invariant
    int incl = v;
#pragma unroll
    for (int o = 1; o < 32; o <<= 1) {
        int u = __shfl_up_sync(0xffffffffu, incl, o);
        if (lane >= o) incl += u;
    }
    if (lane == 31) wsum[w] = incl;
    __syncthreads();
    if (w == 0 && lane < 8) {
        int s = wsum[lane];
#pragma unroll
        for (int o = 1; o < 8; o <<= 1) {
            int u = __shfl_up_sync(0x000000ffu, s, o);
            if (lane >= o) s += u;
        }
        wsum[lane] = s;
    }
    __syncthreads();
    int excl = incl - v + (w > 0 ? wsum[w - 1] : 0);
    if (i < n) g_row[i] = excl;
    if (tid == 0) g_bsum[blockIdx.x] = wsum[7];
}

// ---------------------------------------------------------------------------
// 3: fused block-prefix + offset add + cursor init
// ---------------------------------------------------------------------------
__global__ __launch_bounds__(SCAN_B)
void scanBC_kernel(int nb, int n) {
    __shared__ int wsum[8];
    __shared__ int s_off, s_tot;
    const int tid  = threadIdx.x;
    const int lane = tid & 31;
    const int w    = tid >> 5;

    int v = (tid < nb) ? g_bsum[tid] : 0;
    int incl = v;
#pragma unroll
    for (int o = 1; o < 32; o <<= 1) {
        int u = __shfl_up_sync(0xffffffffu, incl, o);
        if (lane >= o) incl += u;
    }
    if (lane == 31) wsum[w] = incl;
    __syncthreads();
    if (w == 0 && lane < 8) {
        int s = wsum[lane];
#pragma unroll
        for (int o = 1; o < 8; o <<= 1) {
            int u = __shfl_up_sync(0x000000ffu, s, o);
            if (lane >= o) s += u;
        }
        wsum[lane] = s;
    }
    __syncthreads();
    if (tid == (int)blockIdx.x) s_off = incl - v + (w > 0 ? wsum[w - 1] : 0);
    if (tid == 0) s_tot = wsum[7];
    __syncthreads();

    const int i = blockIdx.x * SCAN_B + tid;
    if (i < n) {
        int r = g_row[i] + s_off;
        g_row[i] = r;
        g_cur[i] = r;
    }
    if (blockIdx.x == 0 && tid == 0) g_row[n] = s_tot;
}

// ---------------------------------------------------------------------------
// 4: bucket edges by destination; pack (leaky-score, src) into 8 bytes
//    (1 edge/thread — measured faster than MLP=4 batching; L2-sector-bound)
// ---------------------------------------------------------------------------
__global__ void scatter_kernel(const int* __restrict__ edge_src,
                               const int* __restrict__ edge_dst, int E) {
    int e = blockIdx.x * blockDim.x + threadIdx.x;
    if (e < E) {
        int d = edge_dst[e];
        int s = edge_src[e];
        float sc = g_edst[d] + g_esrc[s];
        sc = sc >= 0.f ? sc : 0.2f * sc;
        int p = atomicAdd(&g_cur[d], 1);
        g_pack[p] = ((unsigned long long)__float_as_uint(sc) << 32) | (unsigned)s;
    }
}

// ---------------------------------------------------------------------------
// 5: per-dst online softmax + weighted aggregation (fp16 gather, fp32 math)
// ---------------------------------------------------------------------------
__global__ __launch_bounds__(256)
void agg_kernel(const float* __restrict__ out_bias,
                float* __restrict__ out, int n) {
    const int gw   = (blockIdx.x * blockDim.x + threadIdx.x) >> 5;
    const int lane = threadIdx.x & 31;
    if (gw >= n) return;

    const int beg = g_row[gw];
    const int end = g_row[gw + 1];

    // pass 1: online max + rescaled exp-sum (coalesced, lane-strided, fp32)
    float m = -INFINITY, ssum = 0.f;
    for (int i = beg + lane; i < end; i += 32) {
        float sc = __uint_as_float((unsigned)(g_pack[i] >> 32));
        if (sc > m) {
            ssum = ssum * __expf(m - sc) + 1.f;
            m = sc;
        } else {
            ssum += __expf(sc - m);
        }
    }
    float M = m;
#pragma unroll
    for (int o = 16; o; o >>= 1) M = fmaxf(M, __shfl_xor_sync(0xffffffffu, M, o));
    float part = (m == -INFINITY) ? 0.f : ssum * __expf(m - M);
#pragma unroll
    for (int o = 16; o; o >>= 1) part += __shfl_xor_sync(0xffffffffu, part, o);
    const float inv = 1.f / fmaxf(part, 1e-12f);

    // pass 2: weighted gather from fp16 h' (256B/edge), fp32 accumulate
    const int hcol = lane * 2;   // half2 col index (covers 4 halves per lane)
    float a0 = 0.f, a1 = 0.f, a2 = 0.f, a3 = 0.f;
    for (int i = beg; i < end; i++) {
        unsigned long long pk = g_pack[i];
        int s = (int)(unsigned)pk;
        float al = __expf(__uint_as_float((unsigned)(pk >> 32)) - M) * inv;
        uint2 u = *(const uint2*)(g_hb + (size_t)s * 64 + hcol);
        float2 f01 = __half22float2(*(__half2*)&u.x);
        float2 f23 = __half22float2(*(__half2*)&u.y);
        a0 += al * f01.x; a1 += al * f01.y; a2 += al * f23.x; a3 += al * f23.y;
    }

    const int c = lane * 4;
    float4 b4 = *(const float4*)(out_bias + c);
    a0 += b4.x; a1 += b4.y; a2 += b4.z; a3 += b4.w;
    float4 o4;
    o4.x = a0 > 0.f ? a0 : expm1f(a0);
    o4.y = a1 > 0.f ? a1 : expm1f(a1);
    o4.z = a2 > 0.f ? a2 : expm1f(a2);
    o4.w = a3 > 0.f ? a3 : expm1f(a3);
    *(float4*)(out + (size_t)gw * ODIM + c) = o4;
}

// ---------------------------------------------------------------------------
extern "C" void kernel_launch(void* const* d_in, const int* in_sizes, int n_in,
                              void* d_out, int out_size) {
    const float* inputs   = (const float*)d_in[0];
    const int*   edge_src = (const int*)d_in[1];
    const int*   edge_dst = (const int*)d_in[2];
    const float* W_seq    = (const float*)d_in[3];
    const float* a_dst    = (const float*)d_in[4];
    const float* b_dst    = (const float*)d_in[5];
    const float* a_src    = (const float*)d_in[6];
    const float* b_src    = (const float*)d_in[7];
    const float* out_bias = (const float*)d_in[8];
    float* out = (float*)d_out;

    const int n = in_sizes[0] / INDIM;
    const int E = in_sizes[1];
    const int nb = (n + SCAN_B - 1) / SCAN_B;
    const int gemm_blocks = (n + 127) / 128;
    const int cnt_blocks  = 1024;

    gemm_fused_kernel<<<gemm_blocks + cnt_blocks, 256>>>(
        inputs, W_seq, a_dst, b_dst, a_src, b_src, edge_dst, n, E, gemm_blocks);
    scanA_kernel<<<nb, SCAN_B>>>(n);
    scanBC_kernel<<<nb, SCAN_B>>>(nb, n);
    scatter_kernel<<<(E + 255) / 256, 256>>>(edge_src, edge_dst, E);
    agg_kernel<<<(n * 32 + 255) / 256, 256>>>(out_bias, out, n);
}